// round 14
// baseline (speedup 1.0000x reference)
#include <cuda_runtime.h>
#include <cuda_bf16.h>
#include <math.h>
#include <stdint.h>

#define B_  4
#define N_  4096
#define D_  244
#define DP_ 256
#define M_  (B_*N_)
#define BAND 7

typedef unsigned long long u64;

// ---- packed fp32x2 helpers (gemm) ----
__device__ __forceinline__ u64 pk2(float lo, float hi) {
    u64 r;
    asm("mov.b64 %0, {%1, %2};" : "=l"(r)
        : "r"(__float_as_uint(lo)), "r"(__float_as_uint(hi)));
    return r;
}
__device__ __forceinline__ u64 dup2(float v) { return pk2(v, v); }
__device__ __forceinline__ void fma2(u64& acc, u64 a, u64 b) {
    asm("fma.rn.f32x2 %0, %1, %2, %0;" : "+l"(acc) : "l"(a), "l"(b));
}
__device__ __forceinline__ float2 up2(u64 v) {
    unsigned lo, hi;
    asm("mov.b64 {%0, %1}, %2;" : "=r"(lo), "=r"(hi) : "l"(v));
    return make_float2(__uint_as_float(lo), __uint_as_float(hi));
}

// fast 2^t on the FMA pipe; exact 0 for t < -126
__device__ __forceinline__ float exp2_fast(float t) {
    const float MAGIC = 12582912.f;
    float r = t + MAGIC;
    float k = r - MAGIC;
    float f = t - k;
    int ik = __float_as_int(r) - 0x4B400000;
    float p = 1.54035304e-4f;
    p = fmaf(p, f, 1.33335581e-3f);
    p = fmaf(p, f, 9.61812911e-3f);
    p = fmaf(p, f, 5.55041087e-2f);
    p = fmaf(p, f, 2.40226507e-1f);
    p = fmaf(p, f, 6.93147182e-1f);
    p = fmaf(p, f, 1.0f);
    float sc = (t >= -126.f) ? __int_as_float((ik + 127) << 23) : 0.f;
    return p * sc;
}

// warp mma: D += A(bf16,row) x B(bf16,col), m16n8k16, fp32 accum
__device__ __forceinline__ void mma_bf16(float* d, const uint32_t* a,
                                         const uint32_t* bb) {
    asm volatile(
        "mma.sync.aligned.m16n8k16.row.col.f32.bf16.bf16.f32 "
        "{%0,%1,%2,%3}, {%4,%5,%6,%7}, {%8,%9}, {%0,%1,%2,%3};"
        : "+f"(d[0]), "+f"(d[1]), "+f"(d[2]), "+f"(d[3])
        : "r"(a[0]), "r"(a[1]), "r"(a[2]), "r"(a[3]),
          "r"(bb[0]), "r"(bb[1]));
}

// split helpers: hi = mantissa-truncate to bf16, lo = rn(residual)
__device__ __forceinline__ void split2(float p0, float p1,
                                       uint32_t& hw, uint32_t& lw) {
    const uint32_t u0 = __float_as_uint(p0) & 0xFFFF0000u;
    const uint32_t u1 = __float_as_uint(p1) & 0xFFFF0000u;
    const float l0 = p0 - __uint_as_float(u0);
    const float l1 = p1 - __uint_as_float(u1);
    hw = u1 | (u0 >> 16);
    asm("cvt.rn.bf16x2.f32 %0, %1, %2;" : "=r"(lw) : "f"(l1), "f"(l0));
}

// ---- scratch ----
__device__ __nv_bfloat16 g_UtH[(size_t)B_ * DP_ * N_];  // [b][c][m] hi split
__device__ __nv_bfloat16 g_UtL[(size_t)B_ * DP_ * N_];  // [b][c][m] lo split
__device__ __nv_bfloat16 g_ShH[(size_t)B_ * N_ * 64];   // shell hi split
__device__ __nv_bfloat16 g_ShL[(size_t)B_ * N_ * 64];   // shell lo split
__device__ float g_Wc[D_ * D_];
__device__ float g_ub[DP_];

// ---------------------------------------------------------------------------
// shell -> split bf16 (hi/lo), elementwise
// ---------------------------------------------------------------------------
__global__ __launch_bounds__(256) void shell_cvt_kernel(
    const float* __restrict__ sh,
    __nv_bfloat16* __restrict__ H, __nv_bfloat16* __restrict__ L)
{
    const int idx = (blockIdx.x * 256 + threadIdx.x) * 4;
    const float4 v = *(const float4*)(sh + idx);
    uint32_t h0, l0, h1, l1;
    split2(v.x, v.y, h0, l0);
    split2(v.z, v.w, h1, l1);
    *(uint2*)((uint32_t*)H + (idx >> 1)) = make_uint2(h0, h1);
    *(uint2*)((uint32_t*)L + (idx >> 1)) = make_uint2(l0, l1);
}

// ---------------------------------------------------------------------------
// Wc = Wo @ Wv ; ub = Wo @ bv
// ---------------------------------------------------------------------------
__global__ __launch_bounds__(256) void wc_kernel(
    const float* __restrict__ Wo, const float* __restrict__ Wv,
    float* __restrict__ Wc)
{
    __shared__ float sWo[16][17];
    __shared__ float sWv[16][17];
    const int tx = threadIdx.x & 15, ty = threadIdx.x >> 4;
    const int c0 = blockIdx.y * 16, k0 = blockIdx.x * 16;
    float acc = 0.f;
    for (int j0 = 0; j0 < D_; j0 += 16) {
        sWo[ty][tx] = (c0 + ty < D_ && j0 + tx < D_) ? Wo[(c0 + ty)*D_ + j0 + tx] : 0.f;
        sWv[ty][tx] = (j0 + ty < D_ && k0 + tx < D_) ? Wv[(j0 + ty)*D_ + k0 + tx] : 0.f;
        __syncthreads();
        #pragma unroll
        for (int jj = 0; jj < 16; jj++) acc += sWo[ty][jj] * sWv[jj][tx];
        __syncthreads();
    }
    if (c0 + ty < D_ && k0 + tx < D_) Wc[(c0 + ty)*D_ + k0 + tx] = acc;
}

__global__ __launch_bounds__(256) void ub_kernel(
    const float* __restrict__ Wo, const float* __restrict__ bv,
    float* __restrict__ ub)
{
    const int c = threadIdx.x;
    float s = 0.f;
    if (c < D_) for (int j = 0; j < D_; j++) s += Wo[c*D_ + j] * bv[j];
    if (c < DP_) ub[c] = (c < D_) ? s : 0.f;
}

// ---------------------------------------------------------------------------
// U = x @ Wc^T + ub, written TRANSPOSED + split bf16:  Ut[b][c][m]
// ---------------------------------------------------------------------------
__global__ __launch_bounds__(256, 2) void gemm_ut_kernel(
    const float* __restrict__ A,
    const float* __restrict__ W,
    const float* __restrict__ bias,
    __nv_bfloat16* __restrict__ UtH,
    __nv_bfloat16* __restrict__ UtL)
{
    __shared__ float AsT[16][132];
    __shared__ float WsT[16][132];
    const int t  = threadIdx.x;
    const int ti = t & 15, tj = t >> 4;
    const int r0 = blockIdx.x * 128;
    const int c0 = blockIdx.y * 128;
    u64 acc2[8][4];
    #pragma unroll
    for (int i = 0; i < 8; i++)
        #pragma unroll
        for (int j = 0; j < 4; j++) acc2[i][j] = 0ull;

    for (int k0 = 0; k0 < 256; k0 += 16) {
        #pragma unroll
        for (int j = 0; j < 2; j++) {
            const int idx = t + j*256;
            const int r = idx >> 2, q = idx & 3;
            const int k = k0 + q*4;
            float4 av = make_float4(0.f,0.f,0.f,0.f);
            if (k < D_) av = *(const float4*)(A + (size_t)(r0 + r) * D_ + k);
            float4 wv = make_float4(0.f,0.f,0.f,0.f);
            const int wr = c0 + r;
            if (k < D_ && wr < D_) wv = *(const float4*)(W + (size_t)wr * D_ + k);
            if (j == 0) __syncthreads();
            AsT[q*4+0][r] = av.x; AsT[q*4+1][r] = av.y;
            AsT[q*4+2][r] = av.z; AsT[q*4+3][r] = av.w;
            WsT[q*4+0][r] = wv.x; WsT[q*4+1][r] = wv.y;
            WsT[q*4+2][r] = wv.z; WsT[q*4+3][r] = wv.w;
        }
        __syncthreads();
        #pragma unroll
        for (int kk = 0; kk < 16; kk++) {
            const ulonglong2 wA = *(const ulonglong2*)&WsT[kk][tj*8];
            const ulonglong2 wB = *(const ulonglong2*)&WsT[kk][tj*8 + 4];
            const u64 wp[4] = {wA.x, wA.y, wB.x, wB.y};
            const float4 a0 = *(const float4*)&AsT[kk][ti*8];
            const float4 a1 = *(const float4*)&AsT[kk][ti*8 + 4];
            const float ar[8] = {a0.x, a0.y, a0.z, a0.w, a1.x, a1.y, a1.z, a1.w};
            #pragma unroll
            for (int i = 0; i < 8; i++) {
                const u64 ad = dup2(ar[i]);
                fma2(acc2[i][0], ad, wp[0]);
                fma2(acc2[i][1], ad, wp[1]);
                fma2(acc2[i][2], ad, wp[2]);
                fma2(acc2[i][3], ad, wp[3]);
            }
        }
    }
    __syncthreads();
    const int rglob = r0 + ti*8;
    const int bb = rglob >> 12;
    const int mm = rglob & (N_-1);
    #pragma unroll
    for (int j2 = 0; j2 < 4; j2++) {
        #pragma unroll
        for (int par = 0; par < 2; par++) {
            const int c = c0 + tj*8 + j2*2 + par;
            const float bz = bias[c];
            uint32_t hw[4], lw[4];
            #pragma unroll
            for (int ii = 0; ii < 4; ii++) {
                float o0, o1;
                { float2 v = up2(acc2[2*ii][j2]);   o0 = (par ? v.y : v.x) + bz; }
                { float2 v = up2(acc2[2*ii+1][j2]); o1 = (par ? v.y : v.x) + bz; }
                split2(o0, o1, hw[ii], lw[ii]);
            }
            const size_t off = ((size_t)bb * DP_ + c) * N_ + mm;
            *(uint4*)(UtH + off) = make_uint4(hw[0], hw[1], hw[2], hw[3]);
            *(uint4*)(UtL + off) = make_uint4(lw[0], lw[1], lw[2], lw[3]);
        }
    }
}

// ---------------------------------------------------------------------------
// Fused attention: mma.sync scores (operands from global split-bf16 shell) +
// in-fragment exp + mma.sync AV. BM=64/CTA, band +-7 tiles (exact truncation).
// ---------------------------------------------------------------------------
#define PPW 36     // p tile pitch in 32-bit words (72 bf16)

__global__ __launch_bounds__(256, 2) void attn_kernel(
    const float* __restrict__ charge,
    const float* __restrict__ mass,
    const float* __restrict__ valence,
    const float* __restrict__ bo,
    float* __restrict__ out)
{
    __shared__ uint32_t pHw[64*PPW];
    __shared__ uint32_t pLw[64*PPW];
    __shared__ float scq[64], ssq[64], sck[64], ssk[64], sfac[64];
    __shared__ float redz[64][2], reds[64][2];

    const int t  = threadIdx.x;
    const int b  = blockIdx.y;
    const int rb = 63 - (int)blockIdx.x;     // heavy row-blocks first
    const int r0 = rb * 64;

    if (t < 64) {
        scq[t] = charge[(size_t)b * N_ + r0 + t];
        ssq[t] = sqrtf(mass[(size_t)b * N_ + r0 + t]);
    }
    __syncthreads();

    const int w    = t >> 5, lane = t & 31;
    const int g    = lane >> 2, tg = lane & 3;
    const int rw   = (w & 3) * 16;           // score row strip
    const int cwsc = (w >> 2) * 32;          // score col strip
    const int cw0  = w * 32;                 // AV output col strip

    const float LC  = -1.44269504f;
    const float LP  = -0.721347520f;
    const float LD_ = -0.432808512f;

    // per-thread row constants (rows rw+g and rw+g+8)
    const int ngA = r0 + rw + g, ngB = ngA + 8;
    const float cqA = LC * scq[rw + g],      cqB = LC * scq[rw + g + 8];
    const float sqA = LC * 0.1f * ssq[rw+g], sqB = LC * 0.1f * ssq[rw+g+8];

    float zA = 0.f, zB = 0.f, sA = 0.f, sB = 0.f;
    float acc[4][4][4];
    #pragma unroll
    for (int mi = 0; mi < 4; mi++)
        #pragma unroll
        for (int ni = 0; ni < 4; ni++)
            #pragma unroll
            for (int q = 0; q < 4; q++) acc[mi][ni][q] = 0.f;

    const int mt_lo = (rb - BAND > 0)  ? rb - BAND : 0;
    const int mt_hi = (rb + BAND < 63) ? rb + BAND : 63;

    const __nv_bfloat16* ShH = g_ShH + (size_t)b * N_ * 64;
    const __nv_bfloat16* ShL = g_ShL + (size_t)b * N_ * 64;
    const __nv_bfloat16* BH0 = g_UtH + (size_t)b * DP_ * N_;
    const __nv_bfloat16* BL0 = g_UtL + (size_t)b * DP_ * N_;

    for (int mt = mt_lo; mt <= mt_hi; mt++) {
        const int  m0 = mt * 64;
        const bool need_av = (mt <= rb);
        __syncthreads();                              // (A)
        if (t < 64) {
            sck[t] = charge[(size_t)b * N_ + m0 + t];
            ssk[t] = sqrtf(mass[(size_t)b * N_ + m0 + t]);
        }
        __syncthreads();                              // (B)

        // ---- scores: P[64x64] = Q @ K^T via mma, operands from global ----
        float psc[4][4];
        #pragma unroll
        for (int ni = 0; ni < 4; ni++)
            #pragma unroll
            for (int q = 0; q < 4; q++) psc[ni][q] = 0.f;
        #pragma unroll
        for (int ks = 0; ks < 4; ks++) {
            const size_t qoff = (size_t)(r0 + rw + g) * 64 + ks*16 + 2*tg;
            uint32_t ah[4], al[4];
            ah[0] = *(const uint32_t*)(ShH + qoff);
            ah[1] = *(const uint32_t*)(ShH + qoff + 512);
            ah[2] = *(const uint32_t*)(ShH + qoff + 8);
            ah[3] = *(const uint32_t*)(ShH + qoff + 520);
            al[0] = *(const uint32_t*)(ShL + qoff);
            al[1] = *(const uint32_t*)(ShL + qoff + 512);
            al[2] = *(const uint32_t*)(ShL + qoff + 8);
            al[3] = *(const uint32_t*)(ShL + qoff + 520);
            #pragma unroll
            for (int ni = 0; ni < 4; ni++) {
                const size_t koff =
                    (size_t)(m0 + cwsc + ni*8 + g) * 64 + ks*16 + 2*tg;
                uint32_t bh[2], bl[2];
                bh[0] = *(const uint32_t*)(ShH + koff);
                bh[1] = *(const uint32_t*)(ShH + koff + 8);
                bl[0] = *(const uint32_t*)(ShL + koff);
                bl[1] = *(const uint32_t*)(ShL + koff + 8);
                mma_bf16(psc[ni], ah, bh);
                mma_bf16(psc[ni], ah, bl);
                mma_bf16(psc[ni], al, bh);
            }
        }
        // ---- energy + exp in fragments; Z/S; p store for AV ----
        #pragma unroll
        for (int ni = 0; ni < 4; ni++) {
            const int lc0 = cwsc + ni*8 + 2*tg;
            const int lc1 = lc0 + 1;
            const float ck0 = sck[lc0], ck1 = sck[lc1];
            const float sk0 = ssk[lc0], sk1 = ssk[lc1];
            const int mg0 = m0 + lc0, mg1 = m0 + lc1;
            float tt, p0, p1, p2, p3;
            tt = fmaf(LP, psc[ni][0], cqA*ck0);
            tt = fmaf(LD_, fabsf((float)(ngA - mg0)), tt);
            p0 = exp2_fast(fmaf(sqA, sk0, tt));
            tt = fmaf(LP, psc[ni][1], cqA*ck1);
            tt = fmaf(LD_, fabsf((float)(ngA - mg1)), tt);
            p1 = exp2_fast(fmaf(sqA, sk1, tt));
            tt = fmaf(LP, psc[ni][2], cqB*ck0);
            tt = fmaf(LD_, fabsf((float)(ngB - mg0)), tt);
            p2 = exp2_fast(fmaf(sqB, sk0, tt));
            tt = fmaf(LP, psc[ni][3], cqB*ck1);
            tt = fmaf(LD_, fabsf((float)(ngB - mg1)), tt);
            p3 = exp2_fast(fmaf(sqB, sk1, tt));
            zA += p0 + p1;  zB += p2 + p3;
            p0 = (mg0 <= ngA) ? p0 : 0.f;
            p1 = (mg1 <= ngA) ? p1 : 0.f;
            p2 = (mg0 <= ngB) ? p2 : 0.f;
            p3 = (mg1 <= ngB) ? p3 : 0.f;
            sA += p0 + p1;  sB += p2 + p3;
            if (need_av) {
                uint32_t hw, lw;
                const int wbase = (cwsc >> 1) + ni*4 + tg;
                split2(p0, p1, hw, lw);
                pHw[(rw+g)*PPW + wbase] = hw;
                pLw[(rw+g)*PPW + wbase] = lw;
                split2(p2, p3, hw, lw);
                pHw[(rw+g+8)*PPW + wbase] = hw;
                pLw[(rw+g+8)*PPW + wbase] = lw;
            }
        }
        if (need_av) {
            __syncthreads();                          // (C) p visible
            #pragma unroll
            for (int ks = 0; ks < 4; ks++) {
                uint32_t bh[4][2], bl[4][2];
                #pragma unroll
                for (int ni = 0; ni < 4; ni++) {
                    const size_t coff =
                        (size_t)(cw0 + ni*8 + g) * N_ + m0 + ks*16 + 2*tg;
                    bh[ni][0] = *(const uint32_t*)(BH0 + coff);
                    bh[ni][1] = *(const uint32_t*)(BH0 + coff + 8);
                    bl[ni][0] = *(const uint32_t*)(BL0 + coff);
                    bl[ni][1] = *(const uint32_t*)(BL0 + coff + 8);
                }
                #pragma unroll
                for (int mi = 0; mi < 4; mi++) {
                    const int wb = (mi*16 + g)*PPW + ks*8 + tg;
                    uint32_t ah[4], al[4];
                    ah[0] = pHw[wb];       ah[1] = pHw[wb + 8*PPW];
                    ah[2] = pHw[wb + 4];   ah[3] = pHw[wb + 8*PPW + 4];
                    al[0] = pLw[wb];       al[1] = pLw[wb + 8*PPW];
                    al[2] = pLw[wb + 4];   al[3] = pLw[wb + 8*PPW + 4];
                    #pragma unroll
                    for (int ni = 0; ni < 4; ni++) {
                        mma_bf16(acc[mi][ni], ah, bh[ni]);
                        mma_bf16(acc[mi][ni], ah, bl[ni]);
                        mma_bf16(acc[mi][ni], al, bh[ni]);
                    }
                }
            }
        }
    }
    // ---- Z/S: quad-shfl then cross-warp-half smem reduce ----
    zA += __shfl_xor_sync(0xffffffffu, zA, 1);
    zA += __shfl_xor_sync(0xffffffffu, zA, 2);
    zB += __shfl_xor_sync(0xffffffffu, zB, 1);
    zB += __shfl_xor_sync(0xffffffffu, zB, 2);
    sA += __shfl_xor_sync(0xffffffffu, sA, 1);
    sA += __shfl_xor_sync(0xffffffffu, sA, 2);
    sB += __shfl_xor_sync(0xffffffffu, sB, 1);
    sB += __shfl_xor_sync(0xffffffffu, sB, 2);
    __syncthreads();
    if (tg == 0) {
        redz[rw+g][w>>2]   = zA;  redz[rw+g+8][w>>2] = zB;
        reds[rw+g][w>>2]   = sA;  reds[rw+g+8][w>>2] = sB;
    }
    __syncthreads();
    if (t < 64) {
        const float Zr = redz[t][0] + redz[t][1];
        const float S  = reds[t][0] + reds[t][1];
        const float val   = valence[(size_t)b * N_ + r0 + t];
        const float scale = fminf(val / (1.f + 1e-6f), 1.f);
        sfac[t] = scale / (scale * S + 1e-8f * Zr);
    }
    __syncthreads();
    // ---- epilogue: scale + bo, direct to out ----
    #pragma unroll
    for (int mi = 0; mi < 4; mi++) {
        const int r1 = mi*16 + g, r2 = r1 + 8;
        const float f1 = sfac[r1], f2 = sfac[r2];
        float* op1 = out + ((size_t)b * N_ + r0 + r1) * D_;
        float* op2 = out + ((size_t)b * N_ + r0 + r2) * D_;
        #pragma unroll
        for (int ni = 0; ni < 4; ni++) {
            const int c1 = cw0 + ni*8 + 2*tg;
            if (c1 < D_ - 1) {
                const float b0v = bo[c1], b1v = bo[c1 + 1];
                *(float2*)(op1 + c1) = make_float2(
                    fmaf(acc[mi][ni][0], f1, b0v), fmaf(acc[mi][ni][1], f1, b1v));
                *(float2*)(op2 + c1) = make_float2(
                    fmaf(acc[mi][ni][2], f2, b0v), fmaf(acc[mi][ni][3], f2, b1v));
            }
        }
    }
}

// ---------------------------------------------------------------------------
extern "C" void kernel_launch(void* const* d_in, const int* in_sizes, int n_in,
                              void* d_out, int out_size)
{
    const float* charge  = (const float*)d_in[0];
    const float* shell   = (const float*)d_in[1];
    const float* mass    = (const float*)d_in[2];
    const float* valence = (const float*)d_in[3];
    // d_in[4] = position (arange; recomputed from indices)
    const float* x       = (const float*)d_in[5];
    const float* Wv      = (const float*)d_in[6];
    const float* bv      = (const float*)d_in[7];
    const float* Wo      = (const float*)d_in[8];
    const float* bo      = (const float*)d_in[9];
    float* out = (float*)d_out;

    void *pWc = nullptr, *pUb = nullptr, *pUtH = nullptr, *pUtL = nullptr;
    void *pShH = nullptr, *pShL = nullptr;
    cudaGetSymbolAddress(&pWc, g_Wc);
    cudaGetSymbolAddress(&pUb, g_ub);
    cudaGetSymbolAddress(&pUtH, g_UtH);
    cudaGetSymbolAddress(&pUtL, g_UtL);
    cudaGetSymbolAddress(&pShH, g_ShH);
    cudaGetSymbolAddress(&pShL, g_ShL);

    shell_cvt_kernel<<<(B_*N_*64)/1024, 256>>>(shell,
                                               (__nv_bfloat16*)pShH,
                                               (__nv_bfloat16*)pShL);
    wc_kernel<<<dim3(16, 16), 256>>>(Wo, Wv, (float*)pWc);
    ub_kernel<<<1, 256>>>(Wo, bv, (float*)pUb);
    gemm_ut_kernel<<<dim3(M_/128, 2), 256>>>(x, (const float*)pWc,
                                             (const float*)pUb,
                                             (__nv_bfloat16*)pUtH,
                                             (__nv_bfloat16*)pUtL);
    attn_kernel<<<dim3(64, B_), 256>>>(charge, mass, valence, bo, out);
}

// round 15
// speedup vs baseline: 1.4515x; 1.4515x over previous
#include <cuda_runtime.h>
#include <cuda_bf16.h>
#include <math.h>
#include <stdint.h>

#define B_  4
#define N_  4096
#define D_  244
#define DP_ 256
#define M_  (B_*N_)
#define BAND 7

typedef unsigned long long u64;

// ---- packed fp32x2 helpers (gemm) ----
__device__ __forceinline__ u64 pk2(float lo, float hi) {
    u64 r;
    asm("mov.b64 %0, {%1, %2};" : "=l"(r)
        : "r"(__float_as_uint(lo)), "r"(__float_as_uint(hi)));
    return r;
}
__device__ __forceinline__ u64 dup2(float v) { return pk2(v, v); }
__device__ __forceinline__ void fma2(u64& acc, u64 a, u64 b) {
    asm("fma.rn.f32x2 %0, %1, %2, %0;" : "+l"(acc) : "l"(a), "l"(b));
}
__device__ __forceinline__ float2 up2(u64 v) {
    unsigned lo, hi;
    asm("mov.b64 {%0, %1}, %2;" : "=r"(lo), "=r"(hi) : "l"(v));
    return make_float2(__uint_as_float(lo), __uint_as_float(hi));
}

// fast 2^t on the FMA pipe; exact 0 for t < -126
__device__ __forceinline__ float exp2_fast(float t) {
    const float MAGIC = 12582912.f;
    float r = t + MAGIC;
    float k = r - MAGIC;
    float f = t - k;
    int ik = __float_as_int(r) - 0x4B400000;
    float p = 1.54035304e-4f;
    p = fmaf(p, f, 1.33335581e-3f);
    p = fmaf(p, f, 9.61812911e-3f);
    p = fmaf(p, f, 5.55041087e-2f);
    p = fmaf(p, f, 2.40226507e-1f);
    p = fmaf(p, f, 6.93147182e-1f);
    p = fmaf(p, f, 1.0f);
    float sc = (t >= -126.f) ? __int_as_float((ik + 127) << 23) : 0.f;
    return p * sc;
}

// warp mma: D += A(bf16,row) x B(bf16,col), m16n8k16, fp32 accum
__device__ __forceinline__ void mma_bf16(float* d, const uint32_t* a,
                                         const uint32_t* bb) {
    asm volatile(
        "mma.sync.aligned.m16n8k16.row.col.f32.bf16.bf16.f32 "
        "{%0,%1,%2,%3}, {%4,%5,%6,%7}, {%8,%9}, {%0,%1,%2,%3};"
        : "+f"(d[0]), "+f"(d[1]), "+f"(d[2]), "+f"(d[3])
        : "r"(a[0]), "r"(a[1]), "r"(a[2]), "r"(a[3]),
          "r"(bb[0]), "r"(bb[1]));
}

// split helpers: hi = mantissa-truncate to bf16, lo = rn(residual)
__device__ __forceinline__ void split2(float p0, float p1,
                                       uint32_t& hw, uint32_t& lw) {
    const uint32_t u0 = __float_as_uint(p0) & 0xFFFF0000u;
    const uint32_t u1 = __float_as_uint(p1) & 0xFFFF0000u;
    const float l0 = p0 - __uint_as_float(u0);
    const float l1 = p1 - __uint_as_float(u1);
    hw = u1 | (u0 >> 16);
    asm("cvt.rn.bf16x2.f32 %0, %1, %2;" : "=r"(lw) : "f"(l1), "f"(l0));
}

// ---- scratch ----
__device__ __nv_bfloat16 g_UtH[(size_t)B_ * DP_ * N_];  // [b][c][m] hi split
__device__ __nv_bfloat16 g_UtL[(size_t)B_ * DP_ * N_];  // [b][c][m] lo split
__device__ float g_Wc[D_ * D_];
__device__ float g_ub[DP_];

// ---------------------------------------------------------------------------
// Wc = Wo @ Wv ; ub = Wo @ bv
// ---------------------------------------------------------------------------
__global__ __launch_bounds__(256) void wc_kernel(
    const float* __restrict__ Wo, const float* __restrict__ Wv,
    float* __restrict__ Wc)
{
    __shared__ float sWo[16][17];
    __shared__ float sWv[16][17];
    const int tx = threadIdx.x & 15, ty = threadIdx.x >> 4;
    const int c0 = blockIdx.y * 16, k0 = blockIdx.x * 16;
    float acc = 0.f;
    for (int j0 = 0; j0 < D_; j0 += 16) {
        sWo[ty][tx] = (c0 + ty < D_ && j0 + tx < D_) ? Wo[(c0 + ty)*D_ + j0 + tx] : 0.f;
        sWv[ty][tx] = (j0 + ty < D_ && k0 + tx < D_) ? Wv[(j0 + ty)*D_ + k0 + tx] : 0.f;
        __syncthreads();
        #pragma unroll
        for (int jj = 0; jj < 16; jj++) acc += sWo[ty][jj] * sWv[jj][tx];
        __syncthreads();
    }
    if (c0 + ty < D_ && k0 + tx < D_) Wc[(c0 + ty)*D_ + k0 + tx] = acc;
}

__global__ __launch_bounds__(256) void ub_kernel(
    const float* __restrict__ Wo, const float* __restrict__ bv,
    float* __restrict__ ub)
{
    const int c = threadIdx.x;
    float s = 0.f;
    if (c < D_) for (int j = 0; j < D_; j++) s += Wo[c*D_ + j] * bv[j];
    if (c < DP_) ub[c] = (c < D_) ? s : 0.f;
}

// ---------------------------------------------------------------------------
// U = x @ Wc^T + ub, written TRANSPOSED + split bf16:  Ut[b][c][m]
// ---------------------------------------------------------------------------
__global__ __launch_bounds__(256, 2) void gemm_ut_kernel(
    const float* __restrict__ A,
    const float* __restrict__ W,
    const float* __restrict__ bias,
    __nv_bfloat16* __restrict__ UtH,
    __nv_bfloat16* __restrict__ UtL)
{
    __shared__ float AsT[16][132];
    __shared__ float WsT[16][132];
    const int t  = threadIdx.x;
    const int ti = t & 15, tj = t >> 4;
    const int r0 = blockIdx.x * 128;
    const int c0 = blockIdx.y * 128;
    u64 acc2[8][4];
    #pragma unroll
    for (int i = 0; i < 8; i++)
        #pragma unroll
        for (int j = 0; j < 4; j++) acc2[i][j] = 0ull;

    for (int k0 = 0; k0 < 256; k0 += 16) {
        #pragma unroll
        for (int j = 0; j < 2; j++) {
            const int idx = t + j*256;
            const int r = idx >> 2, q = idx & 3;
            const int k = k0 + q*4;
            float4 av = make_float4(0.f,0.f,0.f,0.f);
            if (k < D_) av = *(const float4*)(A + (size_t)(r0 + r) * D_ + k);
            float4 wv = make_float4(0.f,0.f,0.f,0.f);
            const int wr = c0 + r;
            if (k < D_ && wr < D_) wv = *(const float4*)(W + (size_t)wr * D_ + k);
            if (j == 0) __syncthreads();
            AsT[q*4+0][r] = av.x; AsT[q*4+1][r] = av.y;
            AsT[q*4+2][r] = av.z; AsT[q*4+3][r] = av.w;
            WsT[q*4+0][r] = wv.x; WsT[q*4+1][r] = wv.y;
            WsT[q*4+2][r] = wv.z; WsT[q*4+3][r] = wv.w;
        }
        __syncthreads();
        #pragma unroll
        for (int kk = 0; kk < 16; kk++) {
            const ulonglong2 wA = *(const ulonglong2*)&WsT[kk][tj*8];
            const ulonglong2 wB = *(const ulonglong2*)&WsT[kk][tj*8 + 4];
            const u64 wp[4] = {wA.x, wA.y, wB.x, wB.y};
            const float4 a0 = *(const float4*)&AsT[kk][ti*8];
            const float4 a1 = *(const float4*)&AsT[kk][ti*8 + 4];
            const float ar[8] = {a0.x, a0.y, a0.z, a0.w, a1.x, a1.y, a1.z, a1.w};
            #pragma unroll
            for (int i = 0; i < 8; i++) {
                const u64 ad = dup2(ar[i]);
                fma2(acc2[i][0], ad, wp[0]);
                fma2(acc2[i][1], ad, wp[1]);
                fma2(acc2[i][2], ad, wp[2]);
                fma2(acc2[i][3], ad, wp[3]);
            }
        }
    }
    __syncthreads();
    const int rglob = r0 + ti*8;
    const int bb = rglob >> 12;
    const int mm = rglob & (N_-1);
    #pragma unroll
    for (int j2 = 0; j2 < 4; j2++) {
        #pragma unroll
        for (int par = 0; par < 2; par++) {
            const int c = c0 + tj*8 + j2*2 + par;
            const float bz = bias[c];
            uint32_t hw[4], lw[4];
            #pragma unroll
            for (int ii = 0; ii < 4; ii++) {
                float o0, o1;
                { float2 v = up2(acc2[2*ii][j2]);   o0 = (par ? v.y : v.x) + bz; }
                { float2 v = up2(acc2[2*ii+1][j2]); o1 = (par ? v.y : v.x) + bz; }
                split2(o0, o1, hw[ii], lw[ii]);
            }
            const size_t off = ((size_t)bb * DP_ + c) * N_ + mm;
            *(uint4*)(UtH + off) = make_uint4(hw[0], hw[1], hw[2], hw[3]);
            *(uint4*)(UtL + off) = make_uint4(lw[0], lw[1], lw[2], lw[3]);
        }
    }
}

// ---------------------------------------------------------------------------
// Fused attention: mma.sync scores (operands staged in smem as split bf16) +
// in-fragment exp + mma.sync AV. BM=64/CTA, band +-7 tiles (exact truncation).
// ---------------------------------------------------------------------------
#define PPW 36     // word pitch for all bf16x2 tiles (conflict-free fragments)

// dynamic smem word offsets
#define O_QH  0
#define O_QL  (64*PPW)
#define O_KH  (2*64*PPW)
#define O_KL  (3*64*PPW)
#define O_PH  (4*64*PPW)
#define O_PL  (5*64*PPW)
#define O_F   (6*64*PPW)          // float section start (words)
#define SMEM_WORDS (O_F + 5*64 + 4*64)
#define SMEM_BYTES (SMEM_WORDS*4)

__global__ __launch_bounds__(256, 2) void attn_kernel(
    const float* __restrict__ charge,
    const float* __restrict__ shell,
    const float* __restrict__ mass,
    const float* __restrict__ valence,
    const float* __restrict__ bo,
    float* __restrict__ out)
{
    extern __shared__ uint32_t smw[];
    uint32_t* qH = smw + O_QH;
    uint32_t* qL = smw + O_QL;
    uint32_t* kH = smw + O_KH;
    uint32_t* kL = smw + O_KL;
    uint32_t* pHw = smw + O_PH;
    uint32_t* pLw = smw + O_PL;
    float* scq  = (float*)(smw + O_F);
    float* ssq  = scq + 64;
    float* sck  = ssq + 64;
    float* ssk  = sck + 64;
    float* sfac = ssk + 64;
    float* redz = sfac + 64;       // [64][2]
    float* reds = redz + 128;      // [64][2]

    const int t  = threadIdx.x;
    const int b  = blockIdx.y;
    const int rb = 63 - (int)blockIdx.x;     // heavy row-blocks first
    const int r0 = rb * 64;

    // q-side: scalars + convert Q shell tile to split-bf16 smem
    {
        const float* shq = shell + ((size_t)b * N_ + r0) * 64;
        #pragma unroll
        for (int j = 0; j < 4; j++) {
            const int idx = t + j*256;
            const int r = idx >> 4, cq = idx & 15;
            const float4 v = *(const float4*)(shq + r*64 + cq*4);
            uint32_t h0, l0, h1, l1;
            split2(v.x, v.y, h0, l0);
            split2(v.z, v.w, h1, l1);
            qH[r*PPW + cq*2]     = h0;  qH[r*PPW + cq*2 + 1] = h1;
            qL[r*PPW + cq*2]     = l0;  qL[r*PPW + cq*2 + 1] = l1;
        }
        if (t < 64) {
            scq[t] = charge[(size_t)b * N_ + r0 + t];
            ssq[t] = sqrtf(mass[(size_t)b * N_ + r0 + t]);
        }
    }
    __syncthreads();

    const int w    = t >> 5, lane = t & 31;
    const int g    = lane >> 2, tg = lane & 3;
    const int rw   = (w & 3) * 16;           // score row strip
    const int cwsc = (w >> 2) * 32;          // score col strip
    const int cw0  = w * 32;                 // AV output col strip

    const float LC  = -1.44269504f;
    const float LP  = -0.721347520f;
    const float LD_ = -0.432808512f;

    const int ngA = r0 + rw + g, ngB = ngA + 8;
    const float cqA = LC * scq[rw + g],      cqB = LC * scq[rw + g + 8];
    const float sqA = LC * 0.1f * ssq[rw+g], sqB = LC * 0.1f * ssq[rw+g+8];

    float zA = 0.f, zB = 0.f, sA = 0.f, sB = 0.f;
    float acc[4][4][4];
    #pragma unroll
    for (int mi = 0; mi < 4; mi++)
        #pragma unroll
        for (int ni = 0; ni < 4; ni++)
            #pragma unroll
            for (int q = 0; q < 4; q++) acc[mi][ni][q] = 0.f;

    const int mt_lo = (rb - BAND > 0)  ? rb - BAND : 0;
    const int mt_hi = (rb + BAND < 63) ? rb + BAND : 63;

    const __nv_bfloat16* BH0 = g_UtH + (size_t)b * DP_ * N_;
    const __nv_bfloat16* BL0 = g_UtL + (size_t)b * DP_ * N_;

    for (int mt = mt_lo; mt <= mt_hi; mt++) {
        const int  m0 = mt * 64;
        const bool need_av = (mt <= rb);
        __syncthreads();                              // (A)
        // k-side: scalars + convert K shell tile
        {
            const float* shk = shell + ((size_t)b * N_ + m0) * 64;
            #pragma unroll
            for (int j = 0; j < 4; j++) {
                const int idx = t + j*256;
                const int r = idx >> 4, cq = idx & 15;
                const float4 v = *(const float4*)(shk + r*64 + cq*4);
                uint32_t h0, l0, h1, l1;
                split2(v.x, v.y, h0, l0);
                split2(v.z, v.w, h1, l1);
                kH[r*PPW + cq*2]     = h0;  kH[r*PPW + cq*2 + 1] = h1;
                kL[r*PPW + cq*2]     = l0;  kL[r*PPW + cq*2 + 1] = l1;
            }
            if (t < 64) {
                sck[t] = charge[(size_t)b * N_ + m0 + t];
                ssk[t] = sqrtf(mass[(size_t)b * N_ + m0 + t]);
            }
        }
        __syncthreads();                              // (B)

        // ---- scores: P[64x64] = Q @ K^T via mma, operands from smem ----
        float psc[4][4];
        #pragma unroll
        for (int ni = 0; ni < 4; ni++)
            #pragma unroll
            for (int q = 0; q < 4; q++) psc[ni][q] = 0.f;
        #pragma unroll
        for (int ks = 0; ks < 4; ks++) {
            const int awb = (rw + g)*PPW + ks*8 + tg;
            uint32_t ah[4], al[4];
            ah[0] = qH[awb];       ah[1] = qH[awb + 8*PPW];
            ah[2] = qH[awb + 4];   ah[3] = qH[awb + 8*PPW + 4];
            al[0] = qL[awb];       al[1] = qL[awb + 8*PPW];
            al[2] = qL[awb + 4];   al[3] = qL[awb + 8*PPW + 4];
            #pragma unroll
            for (int ni = 0; ni < 4; ni++) {
                const int bwb = (cwsc + ni*8 + g)*PPW + ks*8 + tg;
                uint32_t bh[2], bl[2];
                bh[0] = kH[bwb];  bh[1] = kH[bwb + 4];
                bl[0] = kL[bwb];  bl[1] = kL[bwb + 4];
                mma_bf16(psc[ni], ah, bh);
                mma_bf16(psc[ni], ah, bl);
                mma_bf16(psc[ni], al, bh);
            }
        }
        // ---- energy + exp in fragments; Z/S; p store for AV ----
        #pragma unroll
        for (int ni = 0; ni < 4; ni++) {
            const int lc0 = cwsc + ni*8 + 2*tg;
            const int lc1 = lc0 + 1;
            const float ck0 = sck[lc0], ck1 = sck[lc1];
            const float sk0 = ssk[lc0], sk1 = ssk[lc1];
            const int mg0 = m0 + lc0, mg1 = m0 + lc1;
            float tt, p0, p1, p2, p3;
            tt = fmaf(LP, psc[ni][0], cqA*ck0);
            tt = fmaf(LD_, fabsf((float)(ngA - mg0)), tt);
            p0 = exp2_fast(fmaf(sqA, sk0, tt));
            tt = fmaf(LP, psc[ni][1], cqA*ck1);
            tt = fmaf(LD_, fabsf((float)(ngA - mg1)), tt);
            p1 = exp2_fast(fmaf(sqA, sk1, tt));
            tt = fmaf(LP, psc[ni][2], cqB*ck0);
            tt = fmaf(LD_, fabsf((float)(ngB - mg0)), tt);
            p2 = exp2_fast(fmaf(sqB, sk0, tt));
            tt = fmaf(LP, psc[ni][3], cqB*ck1);
            tt = fmaf(LD_, fabsf((float)(ngB - mg1)), tt);
            p3 = exp2_fast(fmaf(sqB, sk1, tt));
            zA += p0 + p1;  zB += p2 + p3;
            p0 = (mg0 <= ngA) ? p0 : 0.f;
            p1 = (mg1 <= ngA) ? p1 : 0.f;
            p2 = (mg0 <= ngB) ? p2 : 0.f;
            p3 = (mg1 <= ngB) ? p3 : 0.f;
            sA += p0 + p1;  sB += p2 + p3;
            if (need_av) {
                uint32_t hw, lw;
                const int wbase = (cwsc >> 1) + ni*4 + tg;
                split2(p0, p1, hw, lw);
                pHw[(rw+g)*PPW + wbase] = hw;
                pLw[(rw+g)*PPW + wbase] = lw;
                split2(p2, p3, hw, lw);
                pHw[(rw+g+8)*PPW + wbase] = hw;
                pLw[(rw+g+8)*PPW + wbase] = lw;
            }
        }
        if (need_av) {
            __syncthreads();                          // (C) p visible
            #pragma unroll
            for (int ks = 0; ks < 4; ks++) {
                uint32_t bh[4][2], bl[4][2];
                #pragma unroll
                for (int ni = 0; ni < 4; ni++) {
                    const size_t coff =
                        (size_t)(cw0 + ni*8 + g) * N_ + m0 + ks*16 + 2*tg;
                    bh[ni][0] = *(const uint32_t*)(BH0 + coff);
                    bh[ni][1] = *(const uint32_t*)(BH0 + coff + 8);
                    bl[ni][0] = *(const uint32_t*)(BL0 + coff);
                    bl[ni][1] = *(const uint32_t*)(BL0 + coff + 8);
                }
                #pragma unroll
                for (int mi = 0; mi < 4; mi++) {
                    const int wb = (mi*16 + g)*PPW + ks*8 + tg;
                    uint32_t ah[4], al[4];
                    ah[0] = pHw[wb];       ah[1] = pHw[wb + 8*PPW];
                    ah[2] = pHw[wb + 4];   ah[3] = pHw[wb + 8*PPW + 4];
                    al[0] = pLw[wb];       al[1] = pLw[wb + 8*PPW];
                    al[2] = pLw[wb + 4];   al[3] = pLw[wb + 8*PPW + 4];
                    #pragma unroll
                    for (int ni = 0; ni < 4; ni++) {
                        mma_bf16(acc[mi][ni], ah, bh[ni]);
                        mma_bf16(acc[mi][ni], ah, bl[ni]);
                        mma_bf16(acc[mi][ni], al, bh[ni]);
                    }
                }
            }
        }
    }
    // ---- Z/S: quad-shfl then cross-warp-half smem reduce ----
    zA += __shfl_xor_sync(0xffffffffu, zA, 1);
    zA += __shfl_xor_sync(0xffffffffu, zA, 2);
    zB += __shfl_xor_sync(0xffffffffu, zB, 1);
    zB += __shfl_xor_sync(0xffffffffu, zB, 2);
    sA += __shfl_xor_sync(0xffffffffu, sA, 1);
    sA += __shfl_xor_sync(0xffffffffu, sA, 2);
    sB += __shfl_xor_sync(0xffffffffu, sB, 1);
    sB += __shfl_xor_sync(0xffffffffu, sB, 2);
    __syncthreads();
    if (tg == 0) {
        redz[(rw+g)*2 + (w>>2)]   = zA;  redz[(rw+g+8)*2 + (w>>2)] = zB;
        reds[(rw+g)*2 + (w>>2)]   = sA;  reds[(rw+g+8)*2 + (w>>2)] = sB;
    }
    __syncthreads();
    if (t < 64) {
        const float Zr = redz[t*2] + redz[t*2+1];
        const float S  = reds[t*2] + reds[t*2+1];
        const float val   = valence[(size_t)b * N_ + r0 + t];
        const float scale = fminf(val / (1.f + 1e-6f), 1.f);
        sfac[t] = scale / (scale * S + 1e-8f * Zr);
    }
    __syncthreads();
    // ---- epilogue: scale + bo, direct to out ----
    #pragma unroll
    for (int mi = 0; mi < 4; mi++) {
        const int r1 = mi*16 + g, r2 = r1 + 8;
        const float f1 = sfac[r1], f2 = sfac[r2];
        float* op1 = out + ((size_t)b * N_ + r0 + r1) * D_;
        float* op2 = out + ((size_t)b * N_ + r0 + r2) * D_;
        #pragma unroll
        for (int ni = 0; ni < 4; ni++) {
            const int c1 = cw0 + ni*8 + 2*tg;
            if (c1 < D_ - 1) {
                const float b0v = bo[c1], b1v = bo[c1 + 1];
                *(float2*)(op1 + c1) = make_float2(
                    fmaf(acc[mi][ni][0], f1, b0v), fmaf(acc[mi][ni][1], f1, b1v));
                *(float2*)(op2 + c1) = make_float2(
                    fmaf(acc[mi][ni][2], f2, b0v), fmaf(acc[mi][ni][3], f2, b1v));
            }
        }
    }
}

// ---------------------------------------------------------------------------
extern "C" void kernel_launch(void* const* d_in, const int* in_sizes, int n_in,
                              void* d_out, int out_size)
{
    const float* charge  = (const float*)d_in[0];
    const float* shell   = (const float*)d_in[1];
    const float* mass    = (const float*)d_in[2];
    const float* valence = (const float*)d_in[3];
    // d_in[4] = position (arange; recomputed from indices)
    const float* x       = (const float*)d_in[5];
    const float* Wv      = (const float*)d_in[6];
    const float* bv      = (const float*)d_in[7];
    const float* Wo      = (const float*)d_in[8];
    const float* bo      = (const float*)d_in[9];
    float* out = (float*)d_out;

    void *pWc = nullptr, *pUb = nullptr, *pUtH = nullptr, *pUtL = nullptr;
    cudaGetSymbolAddress(&pWc, g_Wc);
    cudaGetSymbolAddress(&pUb, g_ub);
    cudaGetSymbolAddress(&pUtH, g_UtH);
    cudaGetSymbolAddress(&pUtL, g_UtL);

    cudaFuncSetAttribute(attn_kernel,
                         cudaFuncAttributeMaxDynamicSharedMemorySize, SMEM_BYTES);

    wc_kernel<<<dim3(16, 16), 256>>>(Wo, Wv, (float*)pWc);
    ub_kernel<<<1, 256>>>(Wo, bv, (float*)pUb);
    gemm_ut_kernel<<<dim3(M_/128, 2), 256>>>(x, (const float*)pWc,
                                             (const float*)pUb,
                                             (__nv_bfloat16*)pUtH,
                                             (__nv_bfloat16*)pUtL);
    attn_kernel<<<dim3(64, B_), 256, SMEM_BYTES>>>(charge, shell, mass,
                                                   valence, bo, out);
}

// round 16
// speedup vs baseline: 1.7790x; 1.2256x over previous
#include <cuda_runtime.h>
#include <cuda_bf16.h>
#include <math.h>
#include <stdint.h>

#define B_  4
#define N_  4096
#define D_  244
#define DP_ 256
#define M_  (B_*N_)
#define BAND 7

typedef unsigned long long u64;

// fast 2^t on the FMA pipe; exact 0 for t < -126
__device__ __forceinline__ float exp2_fast(float t) {
    const float MAGIC = 12582912.f;
    float r = t + MAGIC;
    float k = r - MAGIC;
    float f = t - k;
    int ik = __float_as_int(r) - 0x4B400000;
    float p = 1.54035304e-4f;
    p = fmaf(p, f, 1.33335581e-3f);
    p = fmaf(p, f, 9.61812911e-3f);
    p = fmaf(p, f, 5.55041087e-2f);
    p = fmaf(p, f, 2.40226507e-1f);
    p = fmaf(p, f, 6.93147182e-1f);
    p = fmaf(p, f, 1.0f);
    float sc = (t >= -126.f) ? __int_as_float((ik + 127) << 23) : 0.f;
    return p * sc;
}

// warp mma: D += A(bf16,row) x B(bf16,col), m16n8k16, fp32 accum
__device__ __forceinline__ void mma_bf16(float* d, const uint32_t* a,
                                         const uint32_t* bb) {
    asm volatile(
        "mma.sync.aligned.m16n8k16.row.col.f32.bf16.bf16.f32 "
        "{%0,%1,%2,%3}, {%4,%5,%6,%7}, {%8,%9}, {%0,%1,%2,%3};"
        : "+f"(d[0]), "+f"(d[1]), "+f"(d[2]), "+f"(d[3])
        : "r"(a[0]), "r"(a[1]), "r"(a[2]), "r"(a[3]),
          "r"(bb[0]), "r"(bb[1]));
}

// split helpers: hi = mantissa-truncate to bf16, lo = rn(residual)
__device__ __forceinline__ void split2(float p0, float p1,
                                       uint32_t& hw, uint32_t& lw) {
    const uint32_t u0 = __float_as_uint(p0) & 0xFFFF0000u;
    const uint32_t u1 = __float_as_uint(p1) & 0xFFFF0000u;
    const float l0 = p0 - __uint_as_float(u0);
    const float l1 = p1 - __uint_as_float(u1);
    hw = u1 | (u0 >> 16);
    asm("cvt.rn.bf16x2.f32 %0, %1, %2;" : "=r"(lw) : "f"(l1), "f"(l0));
}

// ---- scratch ----
__device__ __nv_bfloat16 g_UtH[(size_t)B_ * DP_ * N_];  // [b][c][m] hi split
__device__ __nv_bfloat16 g_UtL[(size_t)B_ * DP_ * N_];  // [b][c][m] lo split
__device__ float g_Wc[D_ * D_];
__device__ float g_ub[DP_];

// ---------------------------------------------------------------------------
// Wc = Wo @ Wv ; ub = Wo @ bv
// ---------------------------------------------------------------------------
__global__ __launch_bounds__(256) void wc_kernel(
    const float* __restrict__ Wo, const float* __restrict__ Wv,
    float* __restrict__ Wc)
{
    __shared__ float sWo[16][17];
    __shared__ float sWv[16][17];
    const int tx = threadIdx.x & 15, ty = threadIdx.x >> 4;
    const int c0 = blockIdx.y * 16, k0 = blockIdx.x * 16;
    float acc = 0.f;
    for (int j0 = 0; j0 < D_; j0 += 16) {
        sWo[ty][tx] = (c0 + ty < D_ && j0 + tx < D_) ? Wo[(c0 + ty)*D_ + j0 + tx] : 0.f;
        sWv[ty][tx] = (j0 + ty < D_ && k0 + tx < D_) ? Wv[(j0 + ty)*D_ + k0 + tx] : 0.f;
        __syncthreads();
        #pragma unroll
        for (int jj = 0; jj < 16; jj++) acc += sWo[ty][jj] * sWv[jj][tx];
        __syncthreads();
    }
    if (c0 + ty < D_ && k0 + tx < D_) Wc[(c0 + ty)*D_ + k0 + tx] = acc;
}

__global__ __launch_bounds__(256) void ub_kernel(
    const float* __restrict__ Wo, const float* __restrict__ bv,
    float* __restrict__ ub)
{
    const int c = threadIdx.x;
    float s = 0.f;
    if (c < D_) for (int j = 0; j < D_; j++) s += Wo[c*D_ + j] * bv[j];
    if (c < DP_) ub[c] = (c < D_) ? s : 0.f;
}

// ---------------------------------------------------------------------------
// U = x @ Wc^T + ub via mma.sync (split bf16, 3-pass), written TRANSPOSED +
// split bf16 to Ut[b][c][m]. 128x128 tile, K in 4 chunks of 64.
// ---------------------------------------------------------------------------
#define GP 36
#define GSMEM_BYTES (4*128*GP*4)

__global__ __launch_bounds__(256, 2) void gemm_mma_kernel(
    const float* __restrict__ A,
    const float* __restrict__ W,
    const float* __restrict__ bias,
    __nv_bfloat16* __restrict__ UtH,
    __nv_bfloat16* __restrict__ UtL)
{
    extern __shared__ uint32_t sg[];
    uint32_t* xH = sg;
    uint32_t* xL = sg + 128*GP;
    uint32_t* wH = sg + 2*128*GP;
    uint32_t* wL = sg + 3*128*GP;

    const int t = threadIdx.x;
    const int w = t >> 5, lane = t & 31;
    const int g = lane >> 2, tg = lane & 3;
    const int rstrip = (w & 1) * 64;
    const int cstrip = (w >> 1) * 32;
    const int r0g = blockIdx.x * 128;   // token block
    const int c0g = blockIdx.y * 128;   // col block

    float acc[4][4][4];
    #pragma unroll
    for (int mi = 0; mi < 4; mi++)
        #pragma unroll
        for (int ni = 0; ni < 4; ni++)
            #pragma unroll
            for (int q = 0; q < 4; q++) acc[mi][ni][q] = 0.f;

    for (int chunk = 0; chunk < 4; chunk++) {
        const int k0 = chunk * 64;
        __syncthreads();
        #pragma unroll
        for (int j = 0; j < 8; j++) {
            const int idx = t + j*256;
            const int r = idx >> 4, kq = idx & 15;
            const int k = k0 + kq*4;
            float4 av = make_float4(0.f,0.f,0.f,0.f);
            if (k < D_) av = *(const float4*)(A + (size_t)(r0g + r)*D_ + k);
            uint32_t h0, l0, h1, l1;
            split2(av.x, av.y, h0, l0);
            split2(av.z, av.w, h1, l1);
            xH[r*GP + kq*2] = h0;  xH[r*GP + kq*2 + 1] = h1;
            xL[r*GP + kq*2] = l0;  xL[r*GP + kq*2 + 1] = l1;
            float4 wv = make_float4(0.f,0.f,0.f,0.f);
            const int wr = c0g + r;
            if (k < D_ && wr < D_) wv = *(const float4*)(W + (size_t)wr*D_ + k);
            split2(wv.x, wv.y, h0, l0);
            split2(wv.z, wv.w, h1, l1);
            wH[r*GP + kq*2] = h0;  wH[r*GP + kq*2 + 1] = h1;
            wL[r*GP + kq*2] = l0;  wL[r*GP + kq*2 + 1] = l1;
        }
        __syncthreads();
        #pragma unroll
        for (int ks = 0; ks < 4; ks++) {
            uint32_t bh[4][2], bl[4][2];
            #pragma unroll
            for (int ni = 0; ni < 4; ni++) {
                const int bwb = (cstrip + ni*8 + g)*GP + ks*8 + tg;
                bh[ni][0] = wH[bwb];  bh[ni][1] = wH[bwb + 4];
                bl[ni][0] = wL[bwb];  bl[ni][1] = wL[bwb + 4];
            }
            #pragma unroll
            for (int mi = 0; mi < 4; mi++) {
                const int awb = (rstrip + mi*16 + g)*GP + ks*8 + tg;
                uint32_t ah[4], al[4];
                ah[0] = xH[awb];        ah[1] = xH[awb + 8*GP];
                ah[2] = xH[awb + 4];    ah[3] = xH[awb + 8*GP + 4];
                al[0] = xL[awb];        al[1] = xL[awb + 8*GP];
                al[2] = xL[awb + 4];    al[3] = xL[awb + 8*GP + 4];
                #pragma unroll
                for (int ni = 0; ni < 4; ni++) {
                    mma_bf16(acc[mi][ni], ah, bh[ni]);
                    mma_bf16(acc[mi][ni], ah, bl[ni]);
                    mma_bf16(acc[mi][ni], al, bh[ni]);
                }
            }
        }
    }
    __syncthreads();
    // stage transposed split-bf16 C in smem (reuses operand buffers)
    unsigned short* stH = (unsigned short*)sg;          // [128 c][136 r]
    unsigned short* stL = stH + 128*136;
    #pragma unroll
    for (int mi = 0; mi < 4; mi++) {
        #pragma unroll
        for (int ni = 0; ni < 4; ni++) {
            #pragma unroll
            for (int q = 0; q < 4; q++) {
                const int r = rstrip + mi*16 + g + ((q >> 1) ? 8 : 0);
                const int c = cstrip + ni*8 + 2*tg + (q & 1);
                const float v = acc[mi][ni][q] + bias[c0g + c];
                const uint32_t hb = __float_as_uint(v) & 0xFFFF0000u;
                const float lo = v - __uint_as_float(hb);
                stH[c*136 + r] = (unsigned short)(hb >> 16);
                stL[c*136 + r] = __bfloat16_as_ushort(__float2bfloat16(lo));
            }
        }
    }
    __syncthreads();
    // coalesced write: Ut[b][c][m]
    const int bb   = (int)blockIdx.x >> 5;
    const int mloc = ((int)blockIdx.x & 31) * 128;
    const int crow = t >> 4;
    const int toff = (t & 15) * 8;
    #pragma unroll
    for (int cc = 0; cc < 8; cc++) {
        const int c = cc*16 + crow;
        const size_t off = ((size_t)bb*DP_ + c0g + c)*N_ + mloc + toff;
        *(uint4*)(UtH + off) = *(const uint4*)(stH + c*136 + toff);
        *(uint4*)(UtL + off) = *(const uint4*)(stL + c*136 + toff);
    }
}

// ---------------------------------------------------------------------------
// Fused attention (unchanged from R15): mma.sync scores from smem-staged
// split-bf16 shell + in-fragment exp + mma.sync AV. BM=64/CTA, band +-7.
// ---------------------------------------------------------------------------
#define PPW 36

#define O_QH  0
#define O_QL  (64*PPW)
#define O_KH  (2*64*PPW)
#define O_KL  (3*64*PPW)
#define O_PH  (4*64*PPW)
#define O_PL  (5*64*PPW)
#define O_F   (6*64*PPW)
#define SMEM_WORDS (O_F + 5*64 + 4*64)
#define SMEM_BYTES (SMEM_WORDS*4)

__global__ __launch_bounds__(256, 2) void attn_kernel(
    const float* __restrict__ charge,
    const float* __restrict__ shell,
    const float* __restrict__ mass,
    const float* __restrict__ valence,
    const float* __restrict__ bo,
    float* __restrict__ out)
{
    extern __shared__ uint32_t smw[];
    uint32_t* qH = smw + O_QH;
    uint32_t* qL = smw + O_QL;
    uint32_t* kH = smw + O_KH;
    uint32_t* kL = smw + O_KL;
    uint32_t* pHw = smw + O_PH;
    uint32_t* pLw = smw + O_PL;
    float* scq  = (float*)(smw + O_F);
    float* ssq  = scq + 64;
    float* sck  = ssq + 64;
    float* ssk  = sck + 64;
    float* sfac = ssk + 64;
    float* redz = sfac + 64;
    float* reds = redz + 128;

    const int t  = threadIdx.x;
    const int b  = blockIdx.y;
    const int rb = 63 - (int)blockIdx.x;
    const int r0 = rb * 64;

    {
        const float* shq = shell + ((size_t)b * N_ + r0) * 64;
        #pragma unroll
        for (int j = 0; j < 4; j++) {
            const int idx = t + j*256;
            const int r = idx >> 4, cq = idx & 15;
            const float4 v = *(const float4*)(shq + r*64 + cq*4);
            uint32_t h0, l0, h1, l1;
            split2(v.x, v.y, h0, l0);
            split2(v.z, v.w, h1, l1);
            qH[r*PPW + cq*2]     = h0;  qH[r*PPW + cq*2 + 1] = h1;
            qL[r*PPW + cq*2]     = l0;  qL[r*PPW + cq*2 + 1] = l1;
        }
        if (t < 64) {
            scq[t] = charge[(size_t)b * N_ + r0 + t];
            ssq[t] = sqrtf(mass[(size_t)b * N_ + r0 + t]);
        }
    }
    __syncthreads();

    const int w    = t >> 5, lane = t & 31;
    const int g    = lane >> 2, tg = lane & 3;
    const int rw   = (w & 3) * 16;
    const int cwsc = (w >> 2) * 32;
    const int cw0  = w * 32;

    const float LC  = -1.44269504f;
    const float LP  = -0.721347520f;
    const float LD_ = -0.432808512f;

    const int ngA = r0 + rw + g, ngB = ngA + 8;
    const float cqA = LC * scq[rw + g],      cqB = LC * scq[rw + g + 8];
    const float sqA = LC * 0.1f * ssq[rw+g], sqB = LC * 0.1f * ssq[rw+g+8];

    float zA = 0.f, zB = 0.f, sA = 0.f, sB = 0.f;
    float acc[4][4][4];
    #pragma unroll
    for (int mi = 0; mi < 4; mi++)
        #pragma unroll
        for (int ni = 0; ni < 4; ni++)
            #pragma unroll
            for (int q = 0; q < 4; q++) acc[mi][ni][q] = 0.f;

    const int mt_lo = (rb - BAND > 0)  ? rb - BAND : 0;
    const int mt_hi = (rb + BAND < 63) ? rb + BAND : 63;

    const __nv_bfloat16* BH0 = g_UtH + (size_t)b * DP_ * N_;
    const __nv_bfloat16* BL0 = g_UtL + (size_t)b * DP_ * N_;

    for (int mt = mt_lo; mt <= mt_hi; mt++) {
        const int  m0 = mt * 64;
        const bool need_av = (mt <= rb);
        __syncthreads();
        {
            const float* shk = shell + ((size_t)b * N_ + m0) * 64;
            #pragma unroll
            for (int j = 0; j < 4; j++) {
                const int idx = t + j*256;
                const int r = idx >> 4, cq = idx & 15;
                const float4 v = *(const float4*)(shk + r*64 + cq*4);
                uint32_t h0, l0, h1, l1;
                split2(v.x, v.y, h0, l0);
                split2(v.z, v.w, h1, l1);
                kH[r*PPW + cq*2]     = h0;  kH[r*PPW + cq*2 + 1] = h1;
                kL[r*PPW + cq*2]     = l0;  kL[r*PPW + cq*2 + 1] = l1;
            }
            if (t < 64) {
                sck[t] = charge[(size_t)b * N_ + m0 + t];
                ssk[t] = sqrtf(mass[(size_t)b * N_ + m0 + t]);
            }
        }
        __syncthreads();

        float psc[4][4];
        #pragma unroll
        for (int ni = 0; ni < 4; ni++)
            #pragma unroll
            for (int q = 0; q < 4; q++) psc[ni][q] = 0.f;
        #pragma unroll
        for (int ks = 0; ks < 4; ks++) {
            const int awb = (rw + g)*PPW + ks*8 + tg;
            uint32_t ah[4], al[4];
            ah[0] = qH[awb];       ah[1] = qH[awb + 8*PPW];
            ah[2] = qH[awb + 4];   ah[3] = qH[awb + 8*PPW + 4];
            al[0] = qL[awb];       al[1] = qL[awb + 8*PPW];
            al[2] = qL[awb + 4];   al[3] = qL[awb + 8*PPW + 4];
            #pragma unroll
            for (int ni = 0; ni < 4; ni++) {
                const int bwb = (cwsc + ni*8 + g)*PPW + ks*8 + tg;
                uint32_t bh[2], bl[2];
                bh[0] = kH[bwb];  bh[1] = kH[bwb + 4];
                bl[0] = kL[bwb];  bl[1] = kL[bwb + 4];
                mma_bf16(psc[ni], ah, bh);
                mma_bf16(psc[ni], ah, bl);
                mma_bf16(psc[ni], al, bh);
            }
        }
        #pragma unroll
        for (int ni = 0; ni < 4; ni++) {
            const int lc0 = cwsc + ni*8 + 2*tg;
            const int lc1 = lc0 + 1;
            const float ck0 = sck[lc0], ck1 = sck[lc1];
            const float sk0 = ssk[lc0], sk1 = ssk[lc1];
            const int mg0 = m0 + lc0, mg1 = m0 + lc1;
            float tt, p0, p1, p2, p3;
            tt = fmaf(LP, psc[ni][0], cqA*ck0);
            tt = fmaf(LD_, fabsf((float)(ngA - mg0)), tt);
            p0 = exp2_fast(fmaf(sqA, sk0, tt));
            tt = fmaf(LP, psc[ni][1], cqA*ck1);
            tt = fmaf(LD_, fabsf((float)(ngA - mg1)), tt);
            p1 = exp2_fast(fmaf(sqA, sk1, tt));
            tt = fmaf(LP, psc[ni][2], cqB*ck0);
            tt = fmaf(LD_, fabsf((float)(ngB - mg0)), tt);
            p2 = exp2_fast(fmaf(sqB, sk0, tt));
            tt = fmaf(LP, psc[ni][3], cqB*ck1);
            tt = fmaf(LD_, fabsf((float)(ngB - mg1)), tt);
            p3 = exp2_fast(fmaf(sqB, sk1, tt));
            zA += p0 + p1;  zB += p2 + p3;
            p0 = (mg0 <= ngA) ? p0 : 0.f;
            p1 = (mg1 <= ngA) ? p1 : 0.f;
            p2 = (mg0 <= ngB) ? p2 : 0.f;
            p3 = (mg1 <= ngB) ? p3 : 0.f;
            sA += p0 + p1;  sB += p2 + p3;
            if (need_av) {
                uint32_t hw, lw;
                const int wbase = (cwsc >> 1) + ni*4 + tg;
                split2(p0, p1, hw, lw);
                pHw[(rw+g)*PPW + wbase] = hw;
                pLw[(rw+g)*PPW + wbase] = lw;
                split2(p2, p3, hw, lw);
                pHw[(rw+g+8)*PPW + wbase] = hw;
                pLw[(rw+g+8)*PPW + wbase] = lw;
            }
        }
        if (need_av) {
            __syncthreads();
            #pragma unroll
            for (int ks = 0; ks < 4; ks++) {
                uint32_t bh[4][2], bl[4][2];
                #pragma unroll
                for (int ni = 0; ni < 4; ni++) {
                    const size_t coff =
                        (size_t)(cw0 + ni*8 + g) * N_ + m0 + ks*16 + 2*tg;
                    bh[ni][0] = *(const uint32_t*)(BH0 + coff);
                    bh[ni][1] = *(const uint32_t*)(BH0 + coff + 8);
                    bl[ni][0] = *(const uint32_t*)(BL0 + coff);
                    bl[ni][1] = *(const uint32_t*)(BL0 + coff + 8);
                }
                #pragma unroll
                for (int mi = 0; mi < 4; mi++) {
                    const int wb = (mi*16 + g)*PPW + ks*8 + tg;
                    uint32_t ah[4], al[4];
                    ah[0] = pHw[wb];       ah[1] = pHw[wb + 8*PPW];
                    ah[2] = pHw[wb + 4];   ah[3] = pHw[wb + 8*PPW + 4];
                    al[0] = pLw[wb];       al[1] = pLw[wb + 8*PPW];
                    al[2] = pLw[wb + 4];   al[3] = pLw[wb + 8*PPW + 4];
                    #pragma unroll
                    for (int ni = 0; ni < 4; ni++) {
                        mma_bf16(acc[mi][ni], ah, bh[ni]);
                        mma_bf16(acc[mi][ni], ah, bl[ni]);
                        mma_bf16(acc[mi][ni], al, bh[ni]);
                    }
                }
            }
        }
    }
    zA += __shfl_xor_sync(0xffffffffu, zA, 1);
    zA += __shfl_xor_sync(0xffffffffu, zA, 2);
    zB += __shfl_xor_sync(0xffffffffu, zB, 1);
    zB += __shfl_xor_sync(0xffffffffu, zB, 2);
    sA += __shfl_xor_sync(0xffffffffu, sA, 1);
    sA += __shfl_xor_sync(0xffffffffu, sA, 2);
    sB += __shfl_xor_sync(0xffffffffu, sB, 1);
    sB += __shfl_xor_sync(0xffffffffu, sB, 2);
    __syncthreads();
    if (tg == 0) {
        redz[(rw+g)*2 + (w>>2)]   = zA;  redz[(rw+g+8)*2 + (w>>2)] = zB;
        reds[(rw+g)*2 + (w>>2)]   = sA;  reds[(rw+g+8)*2 + (w>>2)] = sB;
    }
    __syncthreads();
    if (t < 64) {
        const float Zr = redz[t*2] + redz[t*2+1];
        const float S  = reds[t*2] + reds[t*2+1];
        const float val   = valence[(size_t)b * N_ + r0 + t];
        const float scale = fminf(val / (1.f + 1e-6f), 1.f);
        sfac[t] = scale / (scale * S + 1e-8f * Zr);
    }
    __syncthreads();
    #pragma unroll
    for (int mi = 0; mi < 4; mi++) {
        const int r1 = mi*16 + g, r2 = r1 + 8;
        const float f1 = sfac[r1], f2 = sfac[r2];
        float* op1 = out + ((size_t)b * N_ + r0 + r1) * D_;
        float* op2 = out + ((size_t)b * N_ + r0 + r2) * D_;
        #pragma unroll
        for (int ni = 0; ni < 4; ni++) {
            const int c1 = cw0 + ni*8 + 2*tg;
            if (c1 < D_ - 1) {
                const float b0v = bo[c1], b1v = bo[c1 + 1];
                *(float2*)(op1 + c1) = make_float2(
                    fmaf(acc[mi][ni][0], f1, b0v), fmaf(acc[mi][ni][1], f1, b1v));
                *(float2*)(op2 + c1) = make_float2(
                    fmaf(acc[mi][ni][2], f2, b0v), fmaf(acc[mi][ni][3], f2, b1v));
            }
        }
    }
}

// ---------------------------------------------------------------------------
extern "C" void kernel_launch(void* const* d_in, const int* in_sizes, int n_in,
                              void* d_out, int out_size)
{
    const float* charge  = (const float*)d_in[0];
    const float* shell   = (const float*)d_in[1];
    const float* mass    = (const float*)d_in[2];
    const float* valence = (const float*)d_in[3];
    // d_in[4] = position (arange; recomputed from indices)
    const float* x       = (const float*)d_in[5];
    const float* Wv      = (const float*)d_in[6];
    const float* bv      = (const float*)d_in[7];
    const float* Wo      = (const float*)d_in[8];
    const float* bo      = (const float*)d_in[9];
    float* out = (float*)d_out;

    void *pWc = nullptr, *pUb = nullptr, *pUtH = nullptr, *pUtL = nullptr;
    cudaGetSymbolAddress(&pWc, g_Wc);
    cudaGetSymbolAddress(&pUb, g_ub);
    cudaGetSymbolAddress(&pUtH, g_UtH);
    cudaGetSymbolAddress(&pUtL, g_UtL);

    cudaFuncSetAttribute(attn_kernel,
                         cudaFuncAttributeMaxDynamicSharedMemorySize, SMEM_BYTES);
    cudaFuncSetAttribute(gemm_mma_kernel,
                         cudaFuncAttributeMaxDynamicSharedMemorySize, GSMEM_BYTES);

    wc_kernel<<<dim3(16, 16), 256>>>(Wo, Wv, (float*)pWc);
    ub_kernel<<<1, 256>>>(Wo, bv, (float*)pUb);
    gemm_mma_kernel<<<dim3(M_/128, 2), 256, GSMEM_BYTES>>>(
        x, (const float*)pWc, (const float*)pUb,
        (__nv_bfloat16*)pUtH, (__nv_bfloat16*)pUtL);
    attn_kernel<<<dim3(64, B_), 256, SMEM_BYTES>>>(charge, shell, mass,
                                                   valence, bo, out);
}

// round 17
// speedup vs baseline: 1.8881x; 1.0613x over previous
#include <cuda_runtime.h>
#include <cuda_bf16.h>
#include <math.h>
#include <stdint.h>

#define B_  4
#define N_  4096
#define D_  244
#define DP_ 256
#define M_  (B_*N_)
#define BAND 6

typedef unsigned long long u64;

// fast 2^t on the FMA pipe; exact 0 for t < -126
__device__ __forceinline__ float exp2_fast(float t) {
    const float MAGIC = 12582912.f;
    float r = t + MAGIC;
    float k = r - MAGIC;
    float f = t - k;
    int ik = __float_as_int(r) - 0x4B400000;
    float p = 1.54035304e-4f;
    p = fmaf(p, f, 1.33335581e-3f);
    p = fmaf(p, f, 9.61812911e-3f);
    p = fmaf(p, f, 5.55041087e-2f);
    p = fmaf(p, f, 2.40226507e-1f);
    p = fmaf(p, f, 6.93147182e-1f);
    p = fmaf(p, f, 1.0f);
    float sc = (t >= -126.f) ? __int_as_float((ik + 127) << 23) : 0.f;
    return p * sc;
}

// warp mma: D += A(bf16,row) x B(bf16,col), m16n8k16, fp32 accum
__device__ __forceinline__ void mma_bf16(float* d, const uint32_t* a,
                                         const uint32_t* bb) {
    asm volatile(
        "mma.sync.aligned.m16n8k16.row.col.f32.bf16.bf16.f32 "
        "{%0,%1,%2,%3}, {%4,%5,%6,%7}, {%8,%9}, {%0,%1,%2,%3};"
        : "+f"(d[0]), "+f"(d[1]), "+f"(d[2]), "+f"(d[3])
        : "r"(a[0]), "r"(a[1]), "r"(a[2]), "r"(a[3]),
          "r"(bb[0]), "r"(bb[1]));
}

// split helpers: hi = mantissa-truncate to bf16, lo = rn(residual)
__device__ __forceinline__ void split2(float p0, float p1,
                                       uint32_t& hw, uint32_t& lw) {
    const uint32_t u0 = __float_as_uint(p0) & 0xFFFF0000u;
    const uint32_t u1 = __float_as_uint(p1) & 0xFFFF0000u;
    const float l0 = p0 - __uint_as_float(u0);
    const float l1 = p1 - __uint_as_float(u1);
    hw = u1 | (u0 >> 16);
    asm("cvt.rn.bf16x2.f32 %0, %1, %2;" : "=r"(lw) : "f"(l1), "f"(l0));
}

// ---- scratch ----
__device__ __nv_bfloat16 g_UtH[(size_t)B_ * DP_ * N_];  // [b][c][m] hi split
__device__ __nv_bfloat16 g_UtL[(size_t)B_ * DP_ * N_];  // [b][c][m] lo split
__device__ float g_Wc[D_ * D_];
__device__ float g_ub[DP_];

// ---------------------------------------------------------------------------
// Wc = Wo @ Wv ; ub = Wo @ bv
// ---------------------------------------------------------------------------
__global__ __launch_bounds__(256) void wc_kernel(
    const float* __restrict__ Wo, const float* __restrict__ Wv,
    float* __restrict__ Wc)
{
    __shared__ float sWo[16][17];
    __shared__ float sWv[16][17];
    const int tx = threadIdx.x & 15, ty = threadIdx.x >> 4;
    const int c0 = blockIdx.y * 16, k0 = blockIdx.x * 16;
    float acc = 0.f;
    for (int j0 = 0; j0 < D_; j0 += 16) {
        sWo[ty][tx] = (c0 + ty < D_ && j0 + tx < D_) ? Wo[(c0 + ty)*D_ + j0 + tx] : 0.f;
        sWv[ty][tx] = (j0 + ty < D_ && k0 + tx < D_) ? Wv[(j0 + ty)*D_ + k0 + tx] : 0.f;
        __syncthreads();
        #pragma unroll
        for (int jj = 0; jj < 16; jj++) acc += sWo[ty][jj] * sWv[jj][tx];
        __syncthreads();
    }
    if (c0 + ty < D_ && k0 + tx < D_) Wc[(c0 + ty)*D_ + k0 + tx] = acc;
}

__global__ __launch_bounds__(256) void ub_kernel(
    const float* __restrict__ Wo, const float* __restrict__ bv,
    float* __restrict__ ub)
{
    const int c = threadIdx.x;
    float s = 0.f;
    if (c < D_) for (int j = 0; j < D_; j++) s += Wo[c*D_ + j] * bv[j];
    if (c < DP_) ub[c] = (c < D_) ? s : 0.f;
}

// ---------------------------------------------------------------------------
// U = x @ Wc^T + ub via mma.sync (split bf16, 3-pass), written TRANSPOSED +
// split bf16 to Ut[b][c][m]. 128x128 tile, K in 4 chunks of 64.
// ---------------------------------------------------------------------------
#define GP 36
#define GSMEM_BYTES (4*128*GP*4)

__global__ __launch_bounds__(256, 2) void gemm_mma_kernel(
    const float* __restrict__ A,
    const float* __restrict__ W,
    const float* __restrict__ bias,
    __nv_bfloat16* __restrict__ UtH,
    __nv_bfloat16* __restrict__ UtL)
{
    extern __shared__ uint32_t sg[];
    uint32_t* xH = sg;
    uint32_t* xL = sg + 128*GP;
    uint32_t* wH = sg + 2*128*GP;
    uint32_t* wL = sg + 3*128*GP;

    const int t = threadIdx.x;
    const int w = t >> 5, lane = t & 31;
    const int g = lane >> 2, tg = lane & 3;
    const int rstrip = (w & 1) * 64;
    const int cstrip = (w >> 1) * 32;
    const int r0g = blockIdx.x * 128;   // token block
    const int c0g = blockIdx.y * 128;   // col block

    float acc[4][4][4];
    #pragma unroll
    for (int mi = 0; mi < 4; mi++)
        #pragma unroll
        for (int ni = 0; ni < 4; ni++)
            #pragma unroll
            for (int q = 0; q < 4; q++) acc[mi][ni][q] = 0.f;

    for (int chunk = 0; chunk < 4; chunk++) {
        const int k0 = chunk * 64;
        __syncthreads();
        #pragma unroll
        for (int j = 0; j < 8; j++) {
            const int idx = t + j*256;
            const int r = idx >> 4, kq = idx & 15;
            const int k = k0 + kq*4;
            float4 av = make_float4(0.f,0.f,0.f,0.f);
            if (k < D_) av = *(const float4*)(A + (size_t)(r0g + r)*D_ + k);
            uint32_t h0, l0, h1, l1;
            split2(av.x, av.y, h0, l0);
            split2(av.z, av.w, h1, l1);
            xH[r*GP + kq*2] = h0;  xH[r*GP + kq*2 + 1] = h1;
            xL[r*GP + kq*2] = l0;  xL[r*GP + kq*2 + 1] = l1;
            float4 wv = make_float4(0.f,0.f,0.f,0.f);
            const int wr = c0g + r;
            if (k < D_ && wr < D_) wv = *(const float4*)(W + (size_t)wr*D_ + k);
            split2(wv.x, wv.y, h0, l0);
            split2(wv.z, wv.w, h1, l1);
            wH[r*GP + kq*2] = h0;  wH[r*GP + kq*2 + 1] = h1;
            wL[r*GP + kq*2] = l0;  wL[r*GP + kq*2 + 1] = l1;
        }
        __syncthreads();
        #pragma unroll
        for (int ks = 0; ks < 4; ks++) {
            uint32_t bh[4][2], bl[4][2];
            #pragma unroll
            for (int ni = 0; ni < 4; ni++) {
                const int bwb = (cstrip + ni*8 + g)*GP + ks*8 + tg;
                bh[ni][0] = wH[bwb];  bh[ni][1] = wH[bwb + 4];
                bl[ni][0] = wL[bwb];  bl[ni][1] = wL[bwb + 4];
            }
            #pragma unroll
            for (int mi = 0; mi < 4; mi++) {
                const int awb = (rstrip + mi*16 + g)*GP + ks*8 + tg;
                uint32_t ah[4], al[4];
                ah[0] = xH[awb];        ah[1] = xH[awb + 8*GP];
                ah[2] = xH[awb + 4];    ah[3] = xH[awb + 8*GP + 4];
                al[0] = xL[awb];        al[1] = xL[awb + 8*GP];
                al[2] = xL[awb + 4];    al[3] = xL[awb + 8*GP + 4];
                #pragma unroll
                for (int ni = 0; ni < 4; ni++) {
                    mma_bf16(acc[mi][ni], ah, bh[ni]);
                    mma_bf16(acc[mi][ni], ah, bl[ni]);
                    mma_bf16(acc[mi][ni], al, bh[ni]);
                }
            }
        }
    }
    __syncthreads();
    // stage transposed split-bf16 C in smem (reuses operand buffers)
    unsigned short* stH = (unsigned short*)sg;          // [128 c][136 r]
    unsigned short* stL = stH + 128*136;
    #pragma unroll
    for (int mi = 0; mi < 4; mi++) {
        #pragma unroll
        for (int ni = 0; ni < 4; ni++) {
            #pragma unroll
            for (int q = 0; q < 4; q++) {
                const int r = rstrip + mi*16 + g + ((q >> 1) ? 8 : 0);
                const int c = cstrip + ni*8 + 2*tg + (q & 1);
                const float v = acc[mi][ni][q] + bias[c0g + c];
                const uint32_t hb = __float_as_uint(v) & 0xFFFF0000u;
                const float lo = v - __uint_as_float(hb);
                stH[c*136 + r] = (unsigned short)(hb >> 16);
                stL[c*136 + r] = __bfloat16_as_ushort(__float2bfloat16(lo));
            }
        }
    }
    __syncthreads();
    // coalesced write: Ut[b][c][m]
    const int bb   = (int)blockIdx.x >> 5;
    const int mloc = ((int)blockIdx.x & 31) * 128;
    const int crow = t >> 4;
    const int toff = (t & 15) * 8;
    #pragma unroll
    for (int cc = 0; cc < 8; cc++) {
        const int c = cc*16 + crow;
        const size_t off = ((size_t)bb*DP_ + c0g + c)*N_ + mloc + toff;
        *(uint4*)(UtH + off) = *(const uint4*)(stH + c*136 + toff);
        *(uint4*)(UtL + off) = *(const uint4*)(stL + c*136 + toff);
    }
}

// ---------------------------------------------------------------------------
// Fused attention: mma.sync scores + in-fragment exp + mma.sync AV.
// BM=64/CTA, band +-6 tiles. K shell tile DOUBLE-BUFFERED with register
// prefetch (LDG latency hidden behind score+exp); 2 syncs/tile.
// ---------------------------------------------------------------------------
#define PPW 36

#define O_QH  0
#define O_QL  (64*PPW)
#define O_KH  (2*64*PPW)           // [2][64][PPW]
#define O_KL  (4*64*PPW)           // [2][64][PPW]
#define O_PH  (6*64*PPW)
#define O_PL  (7*64*PPW)
#define O_F   (8*64*PPW)
#define SMEM_WORDS (O_F + 2*64 + 2*128 + 64 + 2*128)
#define SMEM_BYTES (SMEM_WORDS*4)

__global__ __launch_bounds__(256, 2) void attn_kernel(
    const float* __restrict__ charge,
    const float* __restrict__ shell,
    const float* __restrict__ mass,
    const float* __restrict__ valence,
    const float* __restrict__ bo,
    float* __restrict__ out)
{
    extern __shared__ uint32_t smw[];
    uint32_t* qH = smw + O_QH;
    uint32_t* qL = smw + O_QL;
    uint32_t* kHb = smw + O_KH;    // [2][64][PPW]
    uint32_t* kLb = smw + O_KL;
    uint32_t* pHw = smw + O_PH;
    uint32_t* pLw = smw + O_PL;
    float* scq  = (float*)(smw + O_F);
    float* ssq  = scq + 64;
    float* sckb = ssq + 64;        // [2][64]
    float* sskb = sckb + 128;      // [2][64]
    float* sfac = sskb + 128;
    float* redz = sfac + 64;       // [64][2]
    float* reds = redz + 128;      // [64][2]

    const int t  = threadIdx.x;
    const int b  = blockIdx.y;
    const int rb = 63 - (int)blockIdx.x;
    const int r0 = rb * 64;

    const int mt_lo = (rb - BAND > 0)  ? rb - BAND : 0;
    const int mt_hi = (rb + BAND < 63) ? rb + BAND : 63;

    // q-side: scalars + convert Q shell tile; prefetch + store first K tile
    {
        const float* shq = shell + ((size_t)b * N_ + r0) * 64;
        #pragma unroll
        for (int j = 0; j < 4; j++) {
            const int idx = t + j*256;
            const int r = idx >> 4, cq = idx & 15;
            const float4 v = *(const float4*)(shq + r*64 + cq*4);
            uint32_t h0, l0, h1, l1;
            split2(v.x, v.y, h0, l0);
            split2(v.z, v.w, h1, l1);
            qH[r*PPW + cq*2]     = h0;  qH[r*PPW + cq*2 + 1] = h1;
            qL[r*PPW + cq*2]     = l0;  qL[r*PPW + cq*2 + 1] = l1;
        }
        if (t < 64) {
            scq[t] = charge[(size_t)b * N_ + r0 + t];
            ssq[t] = sqrtf(mass[(size_t)b * N_ + r0 + t]);
        }
        // first K tile into buffer 0
        const int m0f = mt_lo * 64;
        const float* shk = shell + ((size_t)b * N_ + m0f) * 64;
        #pragma unroll
        for (int j = 0; j < 4; j++) {
            const int idx = t + j*256;
            const int r = idx >> 4, cq = idx & 15;
            const float4 v = *(const float4*)(shk + r*64 + cq*4);
            uint32_t h0, l0, h1, l1;
            split2(v.x, v.y, h0, l0);
            split2(v.z, v.w, h1, l1);
            kHb[r*PPW + cq*2]     = h0;  kHb[r*PPW + cq*2 + 1] = h1;
            kLb[r*PPW + cq*2]     = l0;  kLb[r*PPW + cq*2 + 1] = l1;
        }
        if (t < 64) {
            sckb[t] = charge[(size_t)b * N_ + m0f + t];
            sskb[t] = sqrtf(mass[(size_t)b * N_ + m0f + t]);
        }
    }
    __syncthreads();

    const int w    = t >> 5, lane = t & 31;
    const int g    = lane >> 2, tg = lane & 3;
    const int rw   = (w & 3) * 16;
    const int cwsc = (w >> 2) * 32;
    const int cw0  = w * 32;

    const float LC  = -1.44269504f;
    const float LP  = -0.721347520f;
    const float LD_ = -0.432808512f;

    const int ngA = r0 + rw + g, ngB = ngA + 8;
    const float cqA = LC * scq[rw + g],      cqB = LC * scq[rw + g + 8];
    const float sqA = LC * 0.1f * ssq[rw+g], sqB = LC * 0.1f * ssq[rw+g+8];

    float zA = 0.f, zB = 0.f, sA = 0.f, sB = 0.f;
    float acc[4][4][4];
    #pragma unroll
    for (int mi = 0; mi < 4; mi++)
        #pragma unroll
        for (int ni = 0; ni < 4; ni++)
            #pragma unroll
            for (int q = 0; q < 4; q++) acc[mi][ni][q] = 0.f;

    const __nv_bfloat16* BH0 = g_UtH + (size_t)b * DP_ * N_;
    const __nv_bfloat16* BL0 = g_UtL + (size_t)b * DP_ * N_;

    for (int mt = mt_lo; mt <= mt_hi; mt++) {
        const int  m0 = mt * 64;
        const bool need_av   = (mt <= rb);
        const bool have_next = (mt < mt_hi);
        const int  cur = (mt - mt_lo) & 1, nxt = cur ^ 1;
        uint32_t* kH = kHb + cur*64*PPW;
        uint32_t* kL = kLb + cur*64*PPW;
        float* sck = sckb + cur*64;
        float* ssk = sskb + cur*64;

        // prefetch next K tile (regs) — latency hidden behind score+exp
        float4 pre0, pre1, pre2, pre3;
        float preC = 0.f, preS = 0.f;
        if (have_next) {
            const float* shk = shell + ((size_t)b * N_ + m0 + 64) * 64;
            {
                int idx = t;        pre0 = *(const float4*)(shk + (idx>>4)*64 + (idx&15)*4);
                idx = t + 256;      pre1 = *(const float4*)(shk + (idx>>4)*64 + (idx&15)*4);
                idx = t + 512;      pre2 = *(const float4*)(shk + (idx>>4)*64 + (idx&15)*4);
                idx = t + 768;      pre3 = *(const float4*)(shk + (idx>>4)*64 + (idx&15)*4);
            }
            if (t < 64) {
                preC = charge[(size_t)b * N_ + m0 + 64 + t];
                preS = mass[(size_t)b * N_ + m0 + 64 + t];
            }
        }

        // ---- scores: P[64x64] = Q @ K^T via mma, operands from smem ----
        float psc[4][4];
        #pragma unroll
        for (int ni = 0; ni < 4; ni++)
            #pragma unroll
            for (int q = 0; q < 4; q++) psc[ni][q] = 0.f;
        #pragma unroll
        for (int ks = 0; ks < 4; ks++) {
            const int awb = (rw + g)*PPW + ks*8 + tg;
            uint32_t ah[4], al[4];
            ah[0] = qH[awb];       ah[1] = qH[awb + 8*PPW];
            ah[2] = qH[awb + 4];   ah[3] = qH[awb + 8*PPW + 4];
            al[0] = qL[awb];       al[1] = qL[awb + 8*PPW];
            al[2] = qL[awb + 4];   al[3] = qL[awb + 8*PPW + 4];
            #pragma unroll
            for (int ni = 0; ni < 4; ni++) {
                const int bwb = (cwsc + ni*8 + g)*PPW + ks*8 + tg;
                uint32_t bh[2], bl[2];
                bh[0] = kH[bwb];  bh[1] = kH[bwb + 4];
                bl[0] = kL[bwb];  bl[1] = kL[bwb + 4];
                mma_bf16(psc[ni], ah, bh);
                mma_bf16(psc[ni], ah, bl);
                mma_bf16(psc[ni], al, bh);
            }
        }
        // ---- energy + exp; Z/S ----
        float pm[4][4];
        #pragma unroll
        for (int ni = 0; ni < 4; ni++) {
            const int lc0 = cwsc + ni*8 + 2*tg;
            const int lc1 = lc0 + 1;
            const float ck0 = sck[lc0], ck1 = sck[lc1];
            const float sk0 = ssk[lc0], sk1 = ssk[lc1];
            const int mg0 = m0 + lc0, mg1 = m0 + lc1;
            float tt, p0, p1, p2, p3;
            tt = fmaf(LP, psc[ni][0], cqA*ck0);
            tt = fmaf(LD_, fabsf((float)(ngA - mg0)), tt);
            p0 = exp2_fast(fmaf(sqA, sk0, tt));
            tt = fmaf(LP, psc[ni][1], cqA*ck1);
            tt = fmaf(LD_, fabsf((float)(ngA - mg1)), tt);
            p1 = exp2_fast(fmaf(sqA, sk1, tt));
            tt = fmaf(LP, psc[ni][2], cqB*ck0);
            tt = fmaf(LD_, fabsf((float)(ngB - mg0)), tt);
            p2 = exp2_fast(fmaf(sqB, sk0, tt));
            tt = fmaf(LP, psc[ni][3], cqB*ck1);
            tt = fmaf(LD_, fabsf((float)(ngB - mg1)), tt);
            p3 = exp2_fast(fmaf(sqB, sk1, tt));
            zA += p0 + p1;  zB += p2 + p3;
            p0 = (mg0 <= ngA) ? p0 : 0.f;
            p1 = (mg1 <= ngA) ? p1 : 0.f;
            p2 = (mg0 <= ngB) ? p2 : 0.f;
            p3 = (mg1 <= ngB) ? p3 : 0.f;
            sA += p0 + p1;  sB += p2 + p3;
            pm[ni][0] = p0; pm[ni][1] = p1; pm[ni][2] = p2; pm[ni][3] = p3;
        }
        __syncthreads();   // (W): prev AV done -> safe to overwrite pHw
        if (need_av) {
            #pragma unroll
            for (int ni = 0; ni < 4; ni++) {
                uint32_t hw, lw;
                const int wbase = (cwsc >> 1) + ni*4 + tg;
                split2(pm[ni][0], pm[ni][1], hw, lw);
                pHw[(rw+g)*PPW + wbase] = hw;
                pLw[(rw+g)*PPW + wbase] = lw;
                split2(pm[ni][2], pm[ni][3], hw, lw);
                pHw[(rw+g+8)*PPW + wbase] = hw;
                pLw[(rw+g+8)*PPW + wbase] = lw;
            }
        }
        // convert prefetched K tile into the other buffer
        if (have_next) {
            uint32_t* dH = kHb + nxt*64*PPW;
            uint32_t* dL = kLb + nxt*64*PPW;
            const float4 pr[4] = {pre0, pre1, pre2, pre3};
            #pragma unroll
            for (int j = 0; j < 4; j++) {
                const int idx = t + j*256;
                const int r = idx >> 4, cq = idx & 15;
                uint32_t h0, l0, h1, l1;
                split2(pr[j].x, pr[j].y, h0, l0);
                split2(pr[j].z, pr[j].w, h1, l1);
                dH[r*PPW + cq*2]     = h0;  dH[r*PPW + cq*2 + 1] = h1;
                dL[r*PPW + cq*2]     = l0;  dL[r*PPW + cq*2 + 1] = l1;
            }
            if (t < 64) {
                sckb[nxt*64 + t] = preC;
                sskb[nxt*64 + t] = sqrtf(preS);
            }
        }
        __syncthreads();   // (X): p + next K buffer visible
        if (need_av) {
            #pragma unroll
            for (int ks = 0; ks < 4; ks++) {
                uint32_t bh[4][2], bl[4][2];
                #pragma unroll
                for (int ni = 0; ni < 4; ni++) {
                    const size_t coff =
                        (size_t)(cw0 + ni*8 + g) * N_ + m0 + ks*16 + 2*tg;
                    bh[ni][0] = *(const uint32_t*)(BH0 + coff);
                    bh[ni][1] = *(const uint32_t*)(BH0 + coff + 8);
                    bl[ni][0] = *(const uint32_t*)(BL0 + coff);
                    bl[ni][1] = *(const uint32_t*)(BL0 + coff + 8);
                }
                #pragma unroll
                for (int mi = 0; mi < 4; mi++) {
                    const int wb = (mi*16 + g)*PPW + ks*8 + tg;
                    uint32_t ah[4], al[4];
                    ah[0] = pHw[wb];       ah[1] = pHw[wb + 8*PPW];
                    ah[2] = pHw[wb + 4];   ah[3] = pHw[wb + 8*PPW + 4];
                    al[0] = pLw[wb];       al[1] = pLw[wb + 8*PPW];
                    al[2] = pLw[wb + 4];   al[3] = pLw[wb + 8*PPW + 4];
                    #pragma unroll
                    for (int ni = 0; ni < 4; ni++) {
                        mma_bf16(acc[mi][ni], ah, bh[ni]);
                        mma_bf16(acc[mi][ni], ah, bl[ni]);
                        mma_bf16(acc[mi][ni], al, bh[ni]);
                    }
                }
            }
        }
    }
    // ---- Z/S: quad-shfl then cross-warp-half smem reduce ----
    zA += __shfl_xor_sync(0xffffffffu, zA, 1);
    zA += __shfl_xor_sync(0xffffffffu, zA, 2);
    zB += __shfl_xor_sync(0xffffffffu, zB, 1);
    zB += __shfl_xor_sync(0xffffffffu, zB, 2);
    sA += __shfl_xor_sync(0xffffffffu, sA, 1);
    sA += __shfl_xor_sync(0xffffffffu, sA, 2);
    sB += __shfl_xor_sync(0xffffffffu, sB, 1);
    sB += __shfl_xor_sync(0xffffffffu, sB, 2);
    __syncthreads();
    if (tg == 0) {
        redz[(rw+g)*2 + (w>>2)]   = zA;  redz[(rw+g+8)*2 + (w>>2)] = zB;
        reds[(rw+g)*2 + (w>>2)]   = sA;  reds[(rw+g+8)*2 + (w>>2)] = sB;
    }
    __syncthreads();
    if (t < 64) {
        const float Zr = redz[t*2] + redz[t*2+1];
        const float S  = reds[t*2] + reds[t*2+1];
        const float val   = valence[(size_t)b * N_ + r0 + t];
        const float scale = fminf(val / (1.f + 1e-6f), 1.f);
        sfac[t] = scale / (scale * S + 1e-8f * Zr);
    }
    __syncthreads();
    // ---- epilogue: scale + bo, direct to out ----
    #pragma unroll
    for (int mi = 0; mi < 4; mi++) {
        const int r1 = mi*16 + g, r2 = r1 + 8;
        const float f1 = sfac[r1], f2 = sfac[r2];
        float* op1 = out + ((size_t)b * N_ + r0 + r1) * D_;
        float* op2 = out + ((size_t)b * N_ + r0 + r2) * D_;
        #pragma unroll
        for (int ni = 0; ni < 4; ni++) {
            const int c1 = cw0 + ni*8 + 2*tg;
            if (c1 < D_ - 1) {
                const float b0v = bo[c1], b1v = bo[c1 + 1];
                *(float2*)(op1 + c1) = make_float2(
                    fmaf(acc[mi][ni][0], f1, b0v), fmaf(acc[mi][ni][1], f1, b1v));
                *(float2*)(op2 + c1) = make_float2(
                    fmaf(acc[mi][ni][2], f2, b0v), fmaf(acc[mi][ni][3], f2, b1v));
            }
        }
    }
}

// ---------------------------------------------------------------------------
extern "C" void kernel_launch(void* const* d_in, const int* in_sizes, int n_in,
                              void* d_out, int out_size)
{
    const float* charge  = (const float*)d_in[0];
    const float* shell   = (const float*)d_in[1];
    const float* mass    = (const float*)d_in[2];
    const float* valence = (const float*)d_in[3];
    // d_in[4] = position (arange; recomputed from indices)
    const float* x       = (const float*)d_in[5];
    const float* Wv      = (const float*)d_in[6];
    const float* bv      = (const float*)d_in[7];
    const float* Wo      = (const float*)d_in[8];
    const float* bo      = (const float*)d_in[9];
    float* out = (float*)d_out;

    void *pWc = nullptr, *pUb = nullptr, *pUtH = nullptr, *pUtL = nullptr;
    cudaGetSymbolAddress(&pWc, g_Wc);
    cudaGetSymbolAddress(&pUb, g_ub);
    cudaGetSymbolAddress(&pUtH, g_UtH);
    cudaGetSymbolAddress(&pUtL, g_UtL);

    cudaFuncSetAttribute(attn_kernel,
                         cudaFuncAttributeMaxDynamicSharedMemorySize, SMEM_BYTES);
    cudaFuncSetAttribute(gemm_mma_kernel,
                         cudaFuncAttributeMaxDynamicSharedMemorySize, GSMEM_BYTES);

    wc_kernel<<<dim3(16, 16), 256>>>(Wo, Wv, (float*)pWc);
    ub_kernel<<<1, 256>>>(Wo, bv, (float*)pUb);
    gemm_mma_kernel<<<dim3(M_/128, 2), 256, GSMEM_BYTES>>>(
        x, (const float*)pWc, (const float*)pUb,
        (__nv_bfloat16*)pUtH, (__nv_bfloat16*)pUtL);
    attn_kernel<<<dim3(64, B_), 256, SMEM_BYTES>>>(charge, shell, mass,
                                                   valence, bo, out);
}